// round 4
// baseline (speedup 1.0000x reference)
#include <cuda_runtime.h>
#include <cstdint>

// Problem constants (fixed by the reference: T=8, x shape [T*32, 128, 32, 32])
#define T_STEPS   8
#define BATCH     32
#define CHANNELS  128
#define HW        1024                      // 32*32
#define N_ELEM    (BATCH*CHANNELS*HW)       // 4,194,304 spatial positions
#define NUM_SLABS (N_ELEM/HW)               // 4096 (b,c) channel-slabs; channel = slab%128
#define GRID1     1024                      // single wave; all blocks co-resident
#define MAX_SLABS_PER_BLOCK 16              // stealing bound (avg 4)

// Scratch (static device globals — no runtime allocation permitted).
// g_arrive/g_release are MONOTONIC across graph replays (each replay consumes
// exactly GRID1 arrivals / 1 release). g_ticket is reset by the barrier's
// last arriver AFTER all phase-A stealing is complete (replays are strictly
// sequential on one stream, so this is race-free and deterministic).
__device__ float    g_partials[NUM_SLABS];
__device__ float    g_scale;
__device__ unsigned g_ticket  = 0;
__device__ unsigned g_arrive  = 0;
__device__ unsigned g_release = 0;

// Block-wide deterministic sum (256 threads): shuffle tree + one smem hop.
__device__ __forceinline__ float block_sum_256(float v, float* ws) {
#pragma unroll
    for (int off = 16; off > 0; off >>= 1)
        v += __shfl_down_sync(0xFFFFFFFFu, v, off);
    const int wid = threadIdx.x >> 5;
    if ((threadIdx.x & 31) == 0) ws[wid] = v;
    __syncthreads();
    if (wid == 0) {
        v = (threadIdx.x < 8) ? ws[threadIdx.x] : 0.0f;
#pragma unroll
        for (int off = 4; off > 0; off >>= 1)
            v += __shfl_down_sync(0xFFFFFFFFu, v, off);
    }
    __syncthreads();          // ws reusable afterwards
    return v;                 // valid in thread 0
}

// ---------------------------------------------------------------------------
// Fused persistent kernel with work-stealing:
//   steal slab -> IF recurrence (bits to smem, per-slab partial to gmem)
//   -> grid barrier (last arriver computes scalar scale, resets ticket)
//   -> write the SAME stolen slabs from smem bits * scale.
// ---------------------------------------------------------------------------
__global__ __launch_bounds__(256, 7) void if_fused(const float* __restrict__ x,
                                                   const float* __restrict__ thresh,
                                                   float* __restrict__ out) {
    __shared__ uint32_t s_bits[MAX_SLABS_PER_BLOCK][256];  // packed spike bytes
    __shared__ int      s_slab[MAX_SLABS_PER_BLOCK];
    __shared__ float    s_ws[8];
    __shared__ float    s_scale;
    __shared__ unsigned s_gen;
    __shared__ int      s_last, s_tkt;

    const float thre = __ldg(thresh);
    int nslabs = 0;

    // ---- Phase A: work-stealing IF recurrence ----
    for (;;) {
        if (threadIdx.x == 0) {
            unsigned t = atomicAdd(&g_ticket, 1u);
            s_tkt = (t < NUM_SLABS) ? (int)t : -1;
        }
        __syncthreads();
        const int slab = s_tkt;
        __syncthreads();                       // s_tkt reusable next iter
        if (slab < 0) break;

        const int n = slab * HW + threadIdx.x * 4;

        float4 xv[T_STEPS];
#pragma unroll
        for (int t = 0; t < T_STEPS; t++)
            xv[t] = __ldcs(reinterpret_cast<const float4*>(x + (size_t)t * N_ELEM + n));

        float    mem[4] = {0.5f * thre, 0.5f * thre, 0.5f * thre, 0.5f * thre};
        unsigned sb[4]  = {0u, 0u, 0u, 0u};

#pragma unroll
        for (int t = 0; t < T_STEPS; t++) {
            const float v[4] = {xv[t].x, xv[t].y, xv[t].z, xv[t].w};
#pragma unroll
            for (int j = 0; j < 4; j++) {
                mem[j] += v[j];
                if (mem[j] >= thre) {          // heaviside(mem - cur)
                    mem[j] -= thre;            // mem -= s*cur
                    sb[j]  |= (1u << t);
                }
            }
        }

        s_bits[nslabs][threadIdx.x] = sb[0] | (sb[1] << 8) | (sb[2] << 16) | (sb[3] << 24);
        if (threadIdx.x == 0) s_slab[nslabs] = slab;

        // Compensation pass -> per-element new_thre (cnt via popc).
        float local = 0.0f;
#pragma unroll
        for (int j = 0; j < 4; j++) {
            const int   cnt = __popc(sb[j]);
            const float cv  = fminf((mem[j] - 0.5f * thre) + (float)cnt * thre,
                                    (float)T_STEPS * thre);
            if (cv > 0.0f && cnt > 0)
                local += cv / (float)cnt;
        }
        const float tot = block_sum_256(local, s_ws);
        if (threadIdx.x == 0) g_partials[slab] = tot;

        nslabs++;
        // nslabs can't exceed MAX_SLABS_PER_BLOCK: 4096 slabs / 1024 blocks
        // averages 4; worst case bounded well below 16 since every block
        // draws at least when idle.
    }

    // ---- Grid barrier (generation-counted, monotonic across replays) ----
    if (threadIdx.x == 0) {
        __threadfence();
        const unsigned old = atomicAdd(&g_arrive, 1u);
        s_gen  = old / GRID1;
        s_last = ((old % GRID1) == GRID1 - 1);
    }
    __syncthreads();

    if (s_last) {
        // Per-channel ub (channel = slab % 128, 32 slabs each, fixed order),
        // masked diff, deterministic reduction -> scalar scale.
        float contrib = 0.0f;
        if (threadIdx.x < CHANNELS) {
            float s = 0.0f;
#pragma unroll
            for (int j = 0; j < NUM_SLABS / CHANNELS; j++)
                s += g_partials[threadIdx.x + j * CHANNELS];
            const float ub = s / (float)(BATCH * HW);
            contrib = (thre > ub) ? (ub - thre) : 0.0f;
        }
        const float tot = block_sum_256(contrib, s_ws);
        if (threadIdx.x == 0) {
            g_scale  = thre + 0.2f * tot / (float)CHANNELS;   // LR*2 = 0.2
            g_ticket = 0;                    // safe: all phase-A stealing done
            __threadfence();
            atomicAdd(&g_release, 1u);
        }
    }

    if (threadIdx.x == 0) {
        const unsigned target = s_gen + 1u;
        unsigned v;
        do {
            asm volatile("ld.acquire.gpu.u32 %0, [%1];" : "=r"(v) : "l"(&g_release));
        } while (v < target);
        s_scale = g_scale;
    }
    __syncthreads();

    // ---- Phase B: write the same stolen slabs, bits * scale ----
    const float scale = s_scale;
#pragma unroll 1
    for (int k = 0; k < nslabs; k++) {
        const int      slab = s_slab[k];
        const int      n    = slab * HW + threadIdx.x * 4;
        const uint32_t bits = s_bits[k][threadIdx.x];

#pragma unroll
        for (int t = 0; t < T_STEPS; t++) {
            float4 o;
            o.x = ((bits >> (t))      & 1u) ? scale : 0.0f;
            o.y = ((bits >> (t + 8))  & 1u) ? scale : 0.0f;
            o.z = ((bits >> (t + 16)) & 1u) ? scale : 0.0f;
            o.w = ((bits >> (t + 24)) & 1u) ? scale : 0.0f;
            __stcs(reinterpret_cast<float4*>(out + (size_t)t * N_ELEM + n), o);
        }
    }
}

// ---------------------------------------------------------------------------
extern "C" void kernel_launch(void* const* d_in, const int* in_sizes, int n_in,
                              void* d_out, int out_size) {
    const float* x      = (const float*)d_in[0];   // [T*B, C, H, W] fp32
    const float* thresh = (const float*)d_in[1];   // [1] fp32
    float*       out    = (float*)d_out;

    if_fused<<<GRID1, 256>>>(x, thresh, out);
}